// round 16
// baseline (speedup 1.0000x reference)
#include <cuda_runtime.h>
#include <cuda_bf16.h>
#include <math.h>
#include <stdint.h>
#include <string.h>
#include <limits.h>

#define B    32
#define H    512
#define V    32000
#define TIN  50
#define TOUT 50
#define GRID 128      // persistent blocks (1/SM, all co-resident)
#define NPB  125      // projection blocks (V / VPB)
#define VPB  256      // v-columns per projection block
#define NVT  (V / 16) // 2000 v-tiles
#define NKT  (H / 16) // 32 k-tiles

#define OFF_HT   ((size_t)B * V * TOUT)          // 51,200,000
#define OFF_ATTN (OFF_HT + (size_t)B * H)        // 51,216,384

typedef unsigned long long ull;

// ---------------- device scratch (static, allowed) ----------------
__device__ float g_zbuf[(size_t)TOUT * B * V];   // raw logits, 204.8 MB
__device__ uint4 g_w1f[(size_t)NVT * NKT * 32];  // W_out bf16-hi frags, 32.8 MB
__device__ uint4 g_w2f[(size_t)NVT * NKT * 32];  // W_out bf16-lo frags, 32.8 MB
__device__ unsigned g_hpk[H * B];                // packed (h1,h2) [k][b]
__device__ float g_pmax[NPB][B];
__device__ float g_psum[NPB][B];
__device__ int   g_pidx[NPB][B];
__device__ float g_logZ[TOUT][B];
__device__ float g_h[2][B][H];
__device__ float g_xc[B][H];
__device__ float g_gh[B][3 * H];
__device__ float g_attnx[B][H];
__device__ float g_cattn[B][H];
__device__ int   g_tok[B];
__device__ unsigned g_bar_cnt;                   // monotonic
__device__ unsigned g_bar_gen;                   // monotonic

// ---------------- helpers ----------------
__device__ __forceinline__ ull fma2(ull a, ull b, ull c) {
    ull d;
    asm("fma.rn.f32x2 %0, %1, %2, %3;" : "=l"(d) : "l"(a), "l"(b), "l"(c));
    return d;
}
__device__ __forceinline__ float sum2(ull v) {
    float lo, hi;
    asm("mov.b64 {%0, %1}, %2;" : "=f"(lo), "=f"(hi) : "l"(v));
    return lo + hi;
}
__device__ __forceinline__ ull pk2(float lo, float hi) {
    ull d;
    asm("mov.b64 %0, {%1, %2};" : "=l"(d) : "f"(lo), "f"(hi));
    return d;
}
__device__ __forceinline__ unsigned sm_u32(const void* p) {
    return (unsigned)__cvta_generic_to_shared(p);
}
__device__ __forceinline__ void cpa16(unsigned d, const void* s) {
    asm volatile("cp.async.cg.shared.global [%0], [%1], 16;" :: "r"(d), "l"(s));
}
__device__ __forceinline__ unsigned prmt(unsigned a, unsigned b, unsigned sel) {
    unsigned d;
    asm("prmt.b32 %0, %1, %2, %3;" : "=r"(d) : "r"(a), "r"(b), "r"(sel));
    return d;
}
__device__ __forceinline__ void mma16816(float* d, const uint4& a,
                                         unsigned b0, unsigned b1) {
    asm volatile(
        "mma.sync.aligned.m16n8k16.row.col.f32.bf16.bf16.f32 "
        "{%0,%1,%2,%3}, {%4,%5,%6,%7}, {%8,%9}, {%0,%1,%2,%3};"
        : "+f"(d[0]), "+f"(d[1]), "+f"(d[2]), "+f"(d[3])
        : "r"(a.x), "r"(a.y), "r"(a.z), "r"(a.w), "r"(b0), "r"(b1));
}
// split float2 -> bf16-hi pair word and bf16-residual pair word
__device__ __forceinline__ void cvt2(float2 v, unsigned& o1, unsigned& o2) {
    __nv_bfloat16 ax = __float2bfloat16_rn(v.x), ay = __float2bfloat16_rn(v.y);
    float rx = v.x - __bfloat162float(ax), ry = v.y - __bfloat162float(ay);
    __nv_bfloat16 bx = __float2bfloat16_rn(rx), by = __float2bfloat16_rn(ry);
    unsigned short uax, uay, ubx, uby;
    memcpy(&uax, &ax, 2); memcpy(&uay, &ay, 2);
    memcpy(&ubx, &bx, 2); memcpy(&uby, &by, 2);
    o1 = ((unsigned)uay << 16) | uax;
    o2 = ((unsigned)uby << 16) | ubx;
}
__device__ __forceinline__ unsigned pack_h(float x) {
    __nv_bfloat16 h1 = __float2bfloat16_rn(x);
    float r = x - __bfloat162float(h1);
    __nv_bfloat16 h2 = __float2bfloat16_rn(r);
    unsigned short u1, u2;
    memcpy(&u1, &h1, 2); memcpy(&u2, &h2, 2);
    return ((unsigned)u2 << 16) | u1;
}
// packed (h1,h2) word -> fp32 value (h1 + h2)
__device__ __forceinline__ float unpack_h(unsigned wd) {
    float lo = __uint_as_float(wd << 16);
    float hi = __uint_as_float(wd & 0xFFFF0000u);
    return lo + hi;
}

// Device-wide barrier: monotonic release/acquire (all GRID blocks co-resident).
__device__ __forceinline__ unsigned gsync(unsigned gen) {
    __syncthreads();
    if (threadIdx.x == 0) {
        unsigned next = gen + 1u;
        unsigned old;
        asm volatile("atom.release.gpu.global.add.u32 %0, [%1], %2;"
                     : "=r"(old) : "l"(&g_bar_cnt), "r"(1u) : "memory");
        if (old == next * GRID - 1u) {
            asm volatile("st.release.gpu.global.u32 [%0], %1;"
                         :: "l"(&g_bar_gen), "r"(next) : "memory");
        } else {
            unsigned cur;
            do {
                __nanosleep(32);
                asm volatile("ld.acquire.gpu.global.u32 %0, [%1];"
                             : "=r"(cur) : "l"(&g_bar_gen) : "memory");
            } while ((int)(cur - next) < 0);
        }
    }
    __syncthreads();
    return gen + 1u;
}

// ============================================================================
// P0: convert W_out -> fragment-ordered bf16 split arrays (once)
// ============================================================================
extern "C" __global__ void __launch_bounds__(256)
p0_kernel(const float* __restrict__ W_out) {
    size_t gid = (size_t)blockIdx.x * 256 + threadIdx.x;   // < NVT*NKT*32
    int lane = (int)(gid & 31);
    size_t frag = gid >> 5;
    int kt = (int)(frag & (NKT - 1));
    size_t vt = frag >> 5;
    int g = lane >> 2, tg = lane & 3;
    size_t v0 = vt * 16 + g;
    int k0 = kt * 16 + tg * 2;
    const float* p00 = W_out + v0 * H + k0;
    float2 w00 = *reinterpret_cast<const float2*>(p00);            // a0
    float2 w01 = *reinterpret_cast<const float2*>(p00 + 8);        // a2
    float2 w10 = *reinterpret_cast<const float2*>(p00 + 8 * H);    // a1
    float2 w11 = *reinterpret_cast<const float2*>(p00 + 8 * H + 8);// a3
    uint4 f1, f2;
    cvt2(w00, f1.x, f2.x);
    cvt2(w10, f1.y, f2.y);
    cvt2(w01, f1.z, f2.z);
    cvt2(w11, f1.w, f2.w);
    g_w1f[frag * 32 + lane] = f1;
    g_w2f[frag * 32 + lane] = f2;
}

// ============================================================================
// P1: attn_x = sum_t encoder_out ; h0 = 0 ; attn output = ones ; tok0
// ============================================================================
extern "C" __global__ void p1_kernel(const float* __restrict__ enc,
                                     const int* __restrict__ y,
                                     float* __restrict__ d_out) {
    int gid  = blockIdx.x * blockDim.x + threadIdx.x;
    int nthr = gridDim.x * blockDim.x;
    if (gid < B) g_tok[gid] = y[gid * TOUT];     // y[b][0]
    for (int i = gid; i < B * H; i += nthr) {
        int b = i >> 9, k = i & 511;
        g_h[0][b][k] = 0.f;
        float s = 0.f;
        #pragma unroll 5
        for (int tt = 0; tt < TIN; tt++) s += enc[((size_t)b * TIN + tt) * H + k];
        g_attnx[b][k] = s;
    }
    float4 one4 = make_float4(1.f, 1.f, 1.f, 1.f);
    float4* dst = reinterpret_cast<float4*>(d_out + OFF_ATTN);
    size_t n4 = (size_t)TOUT * B * TIN * H / 4;
    for (size_t i = gid; i < n4; i += nthr) dst[i] = one4;
}

// ============================================================================
// MAIN persistent kernel
//   dynamic smem union:
//     A/B/prologue: inp pairs [32][257] (65792 B) + wtile[2][16][64] (16384 B)
//     C: Pw [512][36] u32 (73728) | HMMA wstage [4w][4st][2KB] (32768)
//        | FFMA fstage [4w][2st][4KB] (32768) | zt [256][33] f32 (33792)
//        -> total 173056 B
// ============================================================================
#define S_PAD 257
#define WST_OFF 73728
#define FST_OFF 106496
#define ZT_OFF  139264
extern "C" __global__ void __launch_bounds__(256, 1)
main_kernel(const float* __restrict__ emb,
            const float* __restrict__ W_comb, const float* __restrict__ b_comb,
            const float* __restrict__ W_hh,  const float* __restrict__ b_hh,
            const float* __restrict__ W_ih,  const float* __restrict__ b_ih,
            const float* __restrict__ W_out, const float* __restrict__ b_out,
            float* __restrict__ d_out) {
    extern __shared__ char dsm[];
    ull* inp = reinterpret_cast<ull*>(dsm);                       // A/B: [32][S_PAD]
    ull* wtile = reinterpret_cast<ull*>(dsm + 65792);             // A/B: [2][16][64]

    __shared__ int   s_tok[B];
    __shared__ float sm_m[8][B], sm_s[8][B], sm_av[8][B];
    __shared__ int   sm_ai[8][B];
    __shared__ float sp[12][33];

    int tid = threadIdx.x, bid = blockIdx.x;
    int lane = tid & 31, w = tid >> 5;
    int g = lane >> 2, tg = lane & 3;
    unsigned gen;
    asm volatile("ld.acquire.gpu.global.u32 %0, [%1];" : "=r"(gen) : "l"(&g_bar_gen));

    // ============== prologue: c_attn (blocks 0..31, A-style) ==============
    if (bid < 32) {
        int row0 = bid * 16;
        const float* wbase = W_comb + H;
        const size_t wstride = 2 * H;
        #pragma unroll
        for (int cc = 0; cc < 2; cc++) {
            #pragma unroll
            for (int p = 0; p < 2; p++) {
                int idx = p * 256 + tid;
                int r = idx >> 5, jj = idx & 31;
                cpa16(sm_u32(&wtile[(size_t)cc * 1024 + r * 64 + jj * 2]),
                      wbase + (size_t)(row0 + r) * wstride + cc * 128 + jj * 4);
            }
            asm volatile("cp.async.commit_group;");
        }
        for (int i = tid; i < B * 256; i += 256) {
            int b = i >> 8, kq = i & 255;
            float2 v = *reinterpret_cast<const float2*>(&g_attnx[b][2 * kq]);
            *reinterpret_cast<float2*>(&inp[b * S_PAD + kq]) = v;
        }
        ull a00 = 0, a01 = 0, a10 = 0, a11 = 0;
        for (int c = 0; c < 4; c++) {
            if (c < 3) asm volatile("cp.async.wait_group 1;");
            else       asm volatile("cp.async.wait_group 0;");
            __syncthreads();
            const ull* wch = wtile + (size_t)(c & 1) * 1024;
            int r0 = (2 * w) * 64, r1 = (2 * w + 1) * 64;
            const ull* xrow = inp + lane * S_PAD + c * 64;
            #pragma unroll 8
            for (int q = 0; q < 64; q += 2) {
                ull x0 = xrow[q], x1 = xrow[q + 1];
                a00 = fma2(wch[r0 + q], x0, a00);
                a01 = fma2(wch[r0 + q + 1], x1, a01);
                a10 = fma2(wch[r1 + q], x0, a10);
                a11 = fma2(wch[r1 + q + 1], x1, a11);
            }
            __syncthreads();
            if (c < 2) {
                #pragma unroll
                for (int p = 0; p < 2; p++) {
                    int idx = p * 256 + tid;
                    int r = idx >> 5, jj = idx & 31;
                    cpa16(sm_u32(&wtile[(size_t)(c & 1) * 1024 + r * 64 + jj * 2]),
                          wbase + (size_t)(row0 + r) * wstride + (c + 2) * 128 + jj * 4);
                }
                asm volatile("cp.async.commit_group;");
            }
        }
        int o0 = row0 + 2 * w;
        g_cattn[lane][o0]     = sum2(a00) + sum2(a01) + b_comb[o0];
        g_cattn[lane][o0 + 1] = sum2(a10) + sum2(a11) + b_comb[o0 + 1];
    }
    gen = gsync(gen);

    int cur = 0;
    for (int t = 0; t < TOUT; t++) {
        // ========= Phase A: (xc blocks: merge->tok) + xc / gh GEMMs =========
        {
            bool is_xc = (bid < 32);
            int row0;
            const float* wbase;
            size_t wstride;
            if (is_xc) { row0 = bid * 16; wbase = W_comb; wstride = 2 * H; }
            else       { row0 = (bid - 32) * 16; wbase = W_hh; wstride = H; }

            #pragma unroll
            for (int cc = 0; cc < 2; cc++) {
                #pragma unroll
                for (int p = 0; p < 2; p++) {
                    int idx = p * 256 + tid;
                    int r = idx >> 5, jj = idx & 31;
                    cpa16(sm_u32(&wtile[(size_t)cc * 1024 + r * 64 + jj * 2]),
                          wbase + (size_t)(row0 + r) * wstride + cc * 128 + jj * 4);
                }
                asm volatile("cp.async.commit_group;");
            }

            if (is_xc) {
                if (t > 0) {
                    int b = lane, part = w;
                    float m = -INFINITY, s = 0.f, av = -INFINITY;
                    int ai = INT_MAX;
                    for (int i = part; i < NPB; i += 8) {
                        float pm = g_pmax[i][b];
                        float ps = g_psum[i][b];
                        int   pi = g_pidx[i][b];
                        if (pm > m) { s = s * expf(m - pm) + ps; m = pm; }
                        else        { s += ps * expf(pm - m); }
                        if (pm > av || (pm == av && pi < ai)) { av = pm; ai = pi; }
                    }
                    sm_m[part][b] = m; sm_s[part][b] = s;
                    sm_av[part][b] = av; sm_ai[part][b] = ai;
                    __syncthreads();
                    if (tid < B) {
                        float M = -INFINITY, S = 0.f, AV = -INFINITY;
                        int AI = INT_MAX;
                        #pragma unroll
                        for (int p = 0; p < 8; p++) {
                            float pm = sm_m[p][tid], ps = sm_s[p][tid];
                            if (pm > M) { S = S * expf(M - pm) + ps; M = pm; }
                            else        { S += ps * expf(pm - M); }
                            float v2 = sm_av[p][tid]; int i2 = sm_ai[p][tid];
                            if (v2 > AV || (v2 == AV && i2 < AI)) { AV = v2; AI = i2; }
                        }
                        s_tok[tid] = AI;
                        if (bid == 0) g_logZ[t - 1][tid] = M + logf(S);
                    }
                } else {
                    if (tid < B) s_tok[tid] = g_tok[tid];
                }
                __syncthreads();
            }

            for (int i = tid; i < B * 256; i += 256) {
                int b = i >> 8, kq = i & 255;
                const float* src = is_xc ? (emb + (size_t)s_tok[b] * H)
                                         : &g_h[cur][b][0];
                float2 v = *reinterpret_cast<const float2*>(src + 2 * kq);
                *reinterpret_cast<float2*>(&inp[b * S_PAD + kq]) = v;
            }

            ull a00 = 0, a01 = 0, a10 = 0, a11 = 0;
            for (int c = 0; c < 4; c++) {
                if (c < 3) asm volatile("cp.async.wait_group 1;");
                else       asm volatile("cp.async.wait_group 0;");
                __syncthreads();
                const ull* wch = wtile + (size_t)(c & 1) * 1024;
                int r0 = (2 * w) * 64, r1 = (2 * w + 1) * 64;
                const ull* xrow = inp + lane * S_PAD + c * 64;
                #pragma unroll 8
                for (int q = 0; q < 64; q += 2) {
                    ull x0 = xrow[q], x1 = xrow[q + 1];
                    a00 = fma2(wch[r0 + q], x0, a00);
                    a01 = fma2(wch[r0 + q + 1], x1, a01);
                    a10 = fma2(wch[r1 + q], x0, a10);
                    a11 = fma2(wch[r1 + q + 1], x1, a11);
                }
                __syncthreads();
                if (c < 2) {
                    #pragma unroll
                    for (int p = 0; p < 2; p++) {
                        int idx = p * 256 + tid;
                        int r = idx >> 5, jj = idx & 31;
                        cpa16(sm_u32(&wtile[(size_t)(c & 1) * 1024 + r * 64 + jj * 2]),
                              wbase + (size_t)(row0 + r) * wstride + (c + 2) * 128 + jj * 4);
                    }
                    asm volatile("cp.async.commit_group;");
                }
            }
            float v0 = sum2(a00) + sum2(a01);
            float v1 = sum2(a10) + sum2(a11);
            int o0 = row0 + 2 * w, o1 = o0 + 1;
            if (is_xc) {
                v0 += g_cattn[lane][o0];
                v1 += g_cattn[lane][o1];
                g_xc[lane][o0] = v0 > 0.f ? v0 : 0.f;
                g_xc[lane][o1] = v1 > 0.f ? v1 : 0.f;
            } else {
                g_gh[lane][o0] = v0 + b_hh[o0];
                g_gh[lane][o1] = v1 + b_hh[o1];
            }
        }
        gen = gsync(gen);

        // ========= Phase B: gi (12 rows/block) + GRU + pack h =========
        {
            int obase = bid * 4;
            #pragma unroll
            for (int cc = 0; cc < 2; cc++) {
                #pragma unroll
                for (int p = 0; p < 2; p++) {
                    int idx = p * 256 + tid;
                    if (idx < 384) {
                        int r = idx >> 5, jj = idx & 31;
                        int gg = r >> 2, ol = r & 3;
                        cpa16(sm_u32(&wtile[(size_t)cc * 1024 + r * 64 + jj * 2]),
                              W_ih + (size_t)(gg * H + obase + ol) * H + cc * 128 + jj * 4);
                    }
                }
                asm volatile("cp.async.commit_group;");
            }
            for (int i = tid; i < B * 256; i += 256) {
                int b = i >> 8, kq = i & 255;
                float2 v = *reinterpret_cast<const float2*>(&g_xc[b][2 * kq]);
                *reinterpret_cast<float2*>(&inp[b * S_PAD + kq]) = v;
            }
            ull a00 = 0, a01 = 0, a10 = 0, a11 = 0;
            for (int c = 0; c < 4; c++) {
                if (c < 3) asm volatile("cp.async.wait_group 1;");
                else       asm volatile("cp.async.wait_group 0;");
                __syncthreads();
                if (w < 6) {
                    const ull* wch = wtile + (size_t)(c & 1) * 1024;
                    int r0 = (2 * w) * 64, r1 = (2 * w + 1) * 64;
                    const ull* xrow = inp + lane * S_PAD + c * 64;
                    #pragma unroll 8
                    for (int q = 0; q < 64; q += 2) {
                        ull x0 = xrow[q], x1 = xrow[q + 1];
                        a00 = fma2(wch[r0 + q], x0, a00);
                        a01 = fma2(wch[r0 + q + 1], x1, a01);
                        a10 = fma2(wch[r1 + q], x0, a10);
                        a11 = fma2(wch[r1 + q + 1], x1, a11);
                    }
                }
                __syncthreads();
                if (c < 2) {
                    #pragma unroll
                    for (int p = 0; p < 2; p++) {
                        int idx = p * 256 + tid;
                        if (idx < 384) {
                            int r = idx >> 5, jj = idx & 31;
                            int gg = r >> 2, ol = r & 3;
                            cpa16(sm_u32(&wtile[(size_t)(c & 1) * 1024 + r * 64 + jj * 2]),
                                  W_ih + (size_t)(gg * H + obase + ol) * H + (c + 2) * 128 + jj * 4);
                        }
                    }
                    asm volatile("cp.async.commit_group;");
                }
            }
            if (w < 6) {
                sp[2 * w][lane]     = sum2(a00) + sum2(a01);
                sp[2 * w + 1][lane] = sum2(a10) + sum2(a11);
            }
            __syncthreads();
            if (tid < 128) {
                int b = tid & 31, ol = tid >> 5;
                int oo = obase + ol;
                float ir  = sp[ol][b]     + b_ih[oo];
                float iz  = sp[4 + ol][b] + b_ih[oo + H];
                float inn = sp[8 + ol][b] + b_ih[oo + 2 * H];
                float r  = 1.f / (1.f + expf(-(ir + g_gh[b][oo])));
                float zz = 1.f / (1.f + expf(-(iz + g_gh[b][oo + H])));
                float n  = tanhf(inn + r * g_gh[b][oo + 2 * H]);
                float hp = g_h[cur][b][oo];
                float hn = (1.f - zz) * n + zz * hp;
                g_h[cur ^ 1][b][oo] = hn;
                g_hpk[oo * 32 + b] = pack_h(hn);
                if (t == TOUT - 1) d_out[OFF_HT + (size_t)b * H + oo] = hn;
            }
        }
        gen = gsync(gen);

        // ========= Phase C: hybrid HMMA (warps 0-3) + f32x2 FFMA (warps 4-7)
        //   warps 0-3: v [vbase, vbase+128)  via bf16x3 mma.sync
        //   warps 4-7: v [vbase+128, vbase+256) via fp32 f32x2 (W_out direct)
        //   One warp of each kind per SMSP -> both pipes saturated.
        if (bid < NPB) {
            unsigned* Pw = reinterpret_cast<unsigned*>(dsm);        // [512][36]
            char* wst = dsm + WST_OFF;                              // [4][4][2KB]
            char* fst = dsm + FST_OFF;                              // [4][2][4KB]
            float* zt = reinterpret_cast<float*>(dsm + ZT_OFF);     // [256][33]
            int vbase = bid * VPB;

            // stage packed h: Pw[k][36] = g_hpk[k][b]
            for (int i = tid; i < 4096; i += 256) {
                int k = i >> 3, b4 = (i & 7) * 4;
                uint4 v = *reinterpret_cast<const uint4*>(&g_hpk[k * 32 + b4]);
                *reinterpret_cast<uint4*>(&Pw[k * 36 + b4]) = v;
            }
            __syncthreads();

            if (w < 4) {
                // -------- HMMA half --------
                size_t gvt0 = (size_t)bid * 16 + 2 * w;
                const uint4* W1p = g_w1f + gvt0 * NKT * 32 + lane;
                const uint4* W2p = g_w2f + gvt0 * NKT * 32 + lane;
                unsigned wsa = sm_u32(wst) + w * 8192 + lane * 16;
                const char* wrd = wst + w * 8192 + lane * 16;

                float acc[2][4][4];
                #pragma unroll
                for (int a = 0; a < 2; a++)
                    #pragma unroll
                    for (int bb = 0; bb < 4; bb++)
                        #pragma unroll
                        for (int cc = 0; cc < 4; cc++) acc[a][bb][cc] = 0.f;

                #pragma unroll
                for (int pre = 0; pre < 3; pre++) {
                    unsigned dst = wsa + pre * 2048;
                    cpa16(dst,        W1p + pre * 32);
                    cpa16(dst + 512,  W2p + pre * 32);
                    cpa16(dst + 1024, W1p + NKT * 32 + pre * 32);
                    cpa16(dst + 1536, W2p + NKT * 32 + pre * 32);
                    asm volatile("cp.async.commit_group;");
                }

                for (int kt = 0; kt < NKT; kt++) {
                    if (kt + 3 < NKT) {
                        int kn = kt + 3;
                        unsigned dst = wsa + (kn & 3) * 2048;
                        cpa16(dst,        W1p + kn * 32);
                        cpa16(dst + 512,  W2p + kn * 32);
                        cpa16(dst + 1024, W1p + NKT * 32 + kn * 32);
                        cpa16(dst + 1536, W2p + NKT * 32 + kn * 32);
                        asm volatile("cp.async.commit_group;");
                        asm volatile("cp.async.wait_group 3;");
                    } else if (kt == NKT - 3) {
                        asm volatile("cp.async.wait_group 2;");
                    } else if (kt == NKT - 2) {
                        asm volatile("cp.async.wait_group 1;");
                    } else {
                        asm volatile("cp.async.wait_group 0;");
                    }

                    const char* stp = wrd + (kt & 3) * 2048;
                    uint4 a1c0 = *reinterpret_cast<const uint4*>(stp);
                    uint4 a2c0 = *reinterpret_cast<const uint4*>(stp + 512);
                    uint4 a1c1 = *reinterpret_cast<const uint4*>(stp + 1024);
                    uint4 a2c1 = *reinterpret_cast<const uint4*>(stp + 1536);

                    unsigned bf1[4][2], bf2[4][2];
                    #pragma unroll
                    for (int bt = 0; bt < 4; bt++) {
                        int n = bt * 8 + g;
                        #pragma unroll
                        for (int r = 0; r < 2; r++) {
                            int k0 = kt * 16 + tg * 2 + r * 8;
                            unsigned e0 = Pw[k0 * 36 + n];
                            unsigned e1 = Pw[(k0 + 1) * 36 + n];
                            bf1[bt][r] = prmt(e0, e1, 0x5410u);
                            bf2[bt][r] = prmt(e0, e1, 0x7632u);
                        }
                    }
                    #pragma unroll
                    for (int bt = 0; bt < 4; bt++) {
                        mma16816(acc[0][bt], a1c0, bf1[bt][0], bf1[bt][1]);
                        mma16816(acc[1][bt], a1c1, bf1[bt][0], bf1[bt][1]);
                    }
                    #pragma unroll
                    for (int bt = 0; bt < 4; bt++) {
                        mma16816(acc[0][bt], a1c0, bf2[bt][0], bf2[bt][1]);
                        mma16816(acc[1][bt], a1c1, bf2[bt][0], bf2[bt][1]);
                    }
                    #pragma unroll
                    for (int bt = 0; bt < 4; bt++) {
                        mma16816(acc[0][bt], a2c0, bf1[bt][0], bf1[bt][1]);
                        mma16816(acc[1][bt], a2c1, bf1[bt][0], bf1[bt][1]);
                    }
                }

                #pragma unroll
                for (int vtl = 0; vtl < 2; vtl++) {
                    int lv0 = (2 * w + vtl) * 16 + g;
                    float bi0 = b_out[vbase + lv0];
                    float bi8 = b_out[vbase + lv0 + 8];
                    #pragma unroll
                    for (int bt = 0; bt < 4; bt++) {
                        int bb = bt * 8 + tg * 2;
                        zt[lv0 * 33 + bb]           = acc[vtl][bt][0] + bi0;
                        zt[lv0 * 33 + bb + 1]       = acc[vtl][bt][1] + bi0;
                        zt[(lv0 + 8) * 33 + bb]     = acc[vtl][bt][2] + bi8;
                        zt[(lv0 + 8) * 33 + bb + 1] = acc[vtl][bt][3] + bi8;
                    }
                }
            } else {
                // -------- FFMA half: warp wf covers 32 v rows, lanes = b ----
                int wf = w - 4;
                int vloc0 = 128 + wf * 32;
                const float* Wr0 = W_out + (size_t)(vbase + vloc0) * H;
                unsigned fsa = sm_u32(fst) + wf * 8192;
                const char* frd = fst + wf * 8192;

                ull acc[32];
                #pragma unroll
                for (int v = 0; v < 32; v++) acc[v] = 0ull;

                // stage issue: chunk c (32 k) -> slot st; 8 cpa16/lane
                auto fissue = [&](int c, int st) {
                    #pragma unroll
                    for (int p = 0; p < 8; p++) {
                        int j = p * 32 + lane;
                        int v = j >> 3, seg = j & 7;
                        cpa16(fsa + st * 4096 + v * 128 + seg * 16,
                              Wr0 + (size_t)v * H + c * 32 + seg * 4);
                    }
                    asm volatile("cp.async.commit_group;");
                };
                fissue(0, 0);
                fissue(1, 1);

                for (int c = 0; c < 16; c++) {
                    if (c < 14) asm volatile("cp.async.wait_group 1;");
                    else        asm volatile("cp.async.wait_group 0;");

                    // build fp32 h pairs for this chunk from Pw
                    ull hp[16];
                    #pragma unroll
                    for (int kk = 0; kk < 16; kk++) {
                        unsigned w0 = Pw[(c * 32 + 2 * kk) * 36 + lane];
                        unsigned w1 = Pw[(c * 32 + 2 * kk + 1) * 36 + lane];
                        hp[kk] = pk2(unpack_h(w0), unpack_h(w1));
                    }
                    const char* stp = frd + (c & 1) * 4096;
                    #pragma unroll
                    for (int v = 0; v < 32; v++) {
                        const ulonglong2* wv =
                            reinterpret_cast<const ulonglong2*>(stp + v * 128);
                        #pragma unroll
                        for (int q = 0; q < 8; q++) {
                            ulonglong2 ww = wv[q];
                            acc[v] = fma2(hp[2 * q],     ww.x, acc[v]);
                            acc[v] = fma2(hp[2 * q + 1], ww.y, acc[v]);
                        }
                    }
                    if (c + 2 < 16) fissue(c + 2, c & 1);
                }

                #pragma unroll
                for (int v = 0; v < 32; v++) {
                    int lv = vloc0 + v;
                    zt[lv * 33 + lane] = sum2(acc[v]) + b_out[vbase + lv];
                }
            }
            __syncthreads();

            // per-(b,seg) partials: warp spans b (conflict-free column reads)
            {
                int b = tid & 31, seg = tid >> 5;
                float m = -INFINITY;
                int mi = 0;
                #pragma unroll 8
                for (int i = 0; i < 32; i++) {
                    int lv = seg * 32 + i;
                    float z = zt[lv * 33 + b];
                    if (z > m) { m = z; mi = vbase + lv; }
                }
                float s = 0.f;
                #pragma unroll 8
                for (int i = 0; i < 32; i++) {
                    int lv = seg * 32 + i;
                    s += expf(zt[lv * 33 + b] - m);
                }
                sm_m[seg][b] = m; sm_s[seg][b] = s; sm_ai[seg][b] = mi;
            }
            // coalesced v-major zbuf writeout
            for (int j = tid; j < B * VPB; j += 256) {
                int b = j >> 8, lv = j & 255;
                __stcs(&g_zbuf[((size_t)t * B + b) * V + vbase + lv],
                       zt[lv * 33 + b]);
            }
            __syncthreads();
            if (tid < B) {
                int b = tid;
                float M = -INFINITY, S = 0.f;
                int I = INT_MAX;
                #pragma unroll
                for (int p = 0; p < 8; p++) {
                    float pm = sm_m[p][b], ps = sm_s[p][b];
                    if (pm > M) { S = S * expf(M - pm) + ps; M = pm; I = sm_ai[p][b]; }
                    else        { S += ps * expf(pm - M); }
                }
                g_pmax[bid][b] = M;
                g_psum[bid][b] = S;
                g_pidx[bid][b] = I;
            }
        }
        gen = gsync(gen);
        cur ^= 1;
    }

    // ---------------- final logZ[TOUT-1] (block 0) ----------------
    if (bid == 0) {
        int b = lane, part = w;
        float m = -INFINITY, s = 0.f;
        for (int i = part; i < NPB; i += 8) {
            float pm = g_pmax[i][b], ps = g_psum[i][b];
            if (pm > m) { s = s * expf(m - pm) + ps; m = pm; }
            else        { s += ps * expf(pm - m); }
        }
        sm_m[part][b] = m; sm_s[part][b] = s;
        __syncthreads();
        if (tid < B) {
            float M = -INFINITY, S = 0.f;
            #pragma unroll
            for (int p = 0; p < 8; p++) {
                float pm = sm_m[p][tid], ps = sm_s[p][tid];
                if (pm > M) { S = S * expf(M - pm) + ps; M = pm; }
                else        { S += ps * expf(pm - M); }
            }
            g_logZ[TOUT - 1][tid] = M + logf(S);
        }
    }
}

// ============================================================================
// E2: out[b][v][t] = z[t][b][v] - logZ[t][b]   (smem-tiled transpose)
// ============================================================================
extern "C" __global__ void __launch_bounds__(256)
e2_kernel(float* __restrict__ d_out) {
    __shared__ float s_z[128][53];
    __shared__ float s_lz[TOUT];
    int b = blockIdx.y;
    int v0 = blockIdx.x * 128;
    int tid = threadIdx.x;
    if (tid < TOUT) s_lz[tid] = g_logZ[tid][b];
    __syncthreads();
    for (int j = tid; j < 128 * TOUT; j += 256) {
        int tt = j >> 7, vl = j & 127;
        s_z[vl][tt] = __ldcs(&g_zbuf[((size_t)tt * B + b) * V + v0 + vl]) - s_lz[tt];
    }
    __syncthreads();
    size_t base = ((size_t)b * V + v0) * TOUT;
    for (int j = tid; j < 128 * TOUT; j += 256) {
        int vl = j / TOUT, tt = j % TOUT;
        d_out[base + j] = s_z[vl][tt];
    }
}

// ============================================================================
extern "C" void kernel_launch(void* const* d_in, const int* in_sizes, int n_in,
                              void* d_out_v, int out_size) {
    const float* enc    = (const float*)d_in[0];
    const int*   y      = (const int*)d_in[1];
    const float* emb    = (const float*)d_in[2];
    // d_in[3..6]: W_fc, b_fc, W_fc1, W_fc2 — dead (softmax over singleton axis)
    const float* W_comb = (const float*)d_in[7];
    const float* b_comb = (const float*)d_in[8];
    const float* W_ih   = (const float*)d_in[9];
    const float* W_hh   = (const float*)d_in[10];
    const float* b_ih   = (const float*)d_in[11];
    const float* b_hh   = (const float*)d_in[12];
    const float* W_out  = (const float*)d_in[13];
    const float* b_out  = (const float*)d_in[14];
    float* d_out = (float*)d_out_v;

    const int main_smem = ZT_OFF + 256 * 33 * 4;   // 173056 (covers A/B's 82176)
    cudaFuncSetAttribute(main_kernel, cudaFuncAttributeMaxDynamicSharedMemorySize,
                         main_smem);

    p0_kernel<<<(NVT * NKT * 32) / 256, 256>>>(W_out);
    p1_kernel<<<512, 256>>>(enc, y, d_out);
    main_kernel<<<GRID, 256, main_smem>>>(emb, W_comb, b_comb, W_hh, b_hh,
                                          W_ih, b_ih, W_out, b_out, d_out);
    e2_kernel<<<dim3(V / 128, B), 256>>>(d_out);
}

// round 17
// speedup vs baseline: 1.4170x; 1.4170x over previous
#include <cuda_runtime.h>
#include <cuda_bf16.h>
#include <math.h>
#include <stdint.h>
#include <string.h>
#include <limits.h>

#define B    32
#define H    512
#define V    32000
#define TIN  50
#define TOUT 50
#define GRID 128      // persistent blocks (1/SM, all co-resident)
#define NPB  125      // projection blocks (V / VPB)
#define VPB  256      // v-columns per projection block
#define NVT  (V / 16) // 2000 v-tiles
#define NKT  (H / 16) // 32 k-tiles

#define OFF_HT   ((size_t)B * V * TOUT)          // 51,200,000
#define OFF_ATTN (OFF_HT + (size_t)B * H)        // 51,216,384

typedef unsigned long long ull;

// ---------------- device scratch (static, allowed) ----------------
__device__ float g_zbuf[(size_t)TOUT * B * V];   // raw logits, 204.8 MB
__device__ uint4 g_w1f[(size_t)NVT * NKT * 32];  // W_out bf16-hi frags, 32.8 MB
__device__ uint4 g_w2f[(size_t)NVT * NKT * 32];  // W_out bf16-lo frags, 32.8 MB
__device__ unsigned g_hpk[H * B];                // packed (h1,h2) [k][b]
__device__ float g_pmax[NPB][B];
__device__ float g_psum[NPB][B];
__device__ int   g_pidx[NPB][B];
__device__ float g_logZ[TOUT][B];
__device__ float g_h[2][B][H];
__device__ float g_xc[B][H];
__device__ float g_gh[B][3 * H];
__device__ float g_attnx[B][H];
__device__ float g_cattn[B][H];
__device__ int   g_tok[B];
__device__ unsigned g_bar_cnt;                   // monotonic; reset at kernel end

// ---------------- helpers ----------------
__device__ __forceinline__ ull fma2(ull a, ull b, ull c) {
    ull d;
    asm("fma.rn.f32x2 %0, %1, %2, %3;" : "=l"(d) : "l"(a), "l"(b), "l"(c));
    return d;
}
__device__ __forceinline__ float sum2(ull v) {
    float lo, hi;
    asm("mov.b64 {%0, %1}, %2;" : "=f"(lo), "=f"(hi) : "l"(v));
    return lo + hi;
}
__device__ __forceinline__ unsigned sm_u32(const void* p) {
    return (unsigned)__cvta_generic_to_shared(p);
}
__device__ __forceinline__ void cpa16(unsigned d, const void* s) {
    asm volatile("cp.async.cg.shared.global [%0], [%1], 16;" :: "r"(d), "l"(s));
}
__device__ __forceinline__ unsigned prmt(unsigned a, unsigned b, unsigned sel) {
    unsigned d;
    asm("prmt.b32 %0, %1, %2, %3;" : "=r"(d) : "r"(a), "r"(b), "r"(sel));
    return d;
}
__device__ __forceinline__ void mma16816(float* d, const uint4& a,
                                         unsigned b0, unsigned b1) {
    asm volatile(
        "mma.sync.aligned.m16n8k16.row.col.f32.bf16.bf16.f32 "
        "{%0,%1,%2,%3}, {%4,%5,%6,%7}, {%8,%9}, {%0,%1,%2,%3};"
        : "+f"(d[0]), "+f"(d[1]), "+f"(d[2]), "+f"(d[3])
        : "r"(a.x), "r"(a.y), "r"(a.z), "r"(a.w), "r"(b0), "r"(b1));
}
// split float2 -> bf16-hi pair word and bf16-residual pair word
__device__ __forceinline__ void cvt2(float2 v, unsigned& o1, unsigned& o2) {
    __nv_bfloat16 ax = __float2bfloat16_rn(v.x), ay = __float2bfloat16_rn(v.y);
    float rx = v.x - __bfloat162float(ax), ry = v.y - __bfloat162float(ay);
    __nv_bfloat16 bx = __float2bfloat16_rn(rx), by = __float2bfloat16_rn(ry);
    unsigned short uax, uay, ubx, uby;
    memcpy(&uax, &ax, 2); memcpy(&uay, &ay, 2);
    memcpy(&ubx, &bx, 2); memcpy(&uby, &by, 2);
    o1 = ((unsigned)uay << 16) | uax;
    o2 = ((unsigned)uby << 16) | ubx;
}
__device__ __forceinline__ unsigned pack_h(float x) {
    __nv_bfloat16 h1 = __float2bfloat16_rn(x);
    float r = x - __bfloat162float(h1);
    __nv_bfloat16 h2 = __float2bfloat16_rn(r);
    unsigned short u1, u2;
    memcpy(&u1, &h1, 2); memcpy(&u2, &h2, 2);
    return ((unsigned)u2 << 16) | u1;
}

// Device-wide barrier: red (no-return) + acquire poll on monotonic counter.
__device__ __forceinline__ unsigned gsync(unsigned gen) {
    __syncthreads();
    if (threadIdx.x == 0) {
        unsigned target = (gen + 1u) * GRID;
        asm volatile("red.release.gpu.global.add.u32 [%0], %1;"
                     :: "l"(&g_bar_cnt), "r"(1u) : "memory");
        unsigned cur;
        asm volatile("ld.acquire.gpu.global.u32 %0, [%1];"
                     : "=r"(cur) : "l"(&g_bar_cnt) : "memory");
        while ((int)(cur - target) < 0) {
            __nanosleep(16);
            asm volatile("ld.acquire.gpu.global.u32 %0, [%1];"
                         : "=r"(cur) : "l"(&g_bar_cnt) : "memory");
        }
    }
    __syncthreads();
    return gen + 1u;
}

// ============================================================================
// P0: convert W_out -> fragment-ordered bf16 split arrays (once)
// ============================================================================
extern "C" __global__ void __launch_bounds__(256)
p0_kernel(const float* __restrict__ W_out) {
    size_t gid = (size_t)blockIdx.x * 256 + threadIdx.x;   // < NVT*NKT*32
    int lane = (int)(gid & 31);
    size_t frag = gid >> 5;
    int kt = (int)(frag & (NKT - 1));
    size_t vt = frag >> 5;
    int g = lane >> 2, tg = lane & 3;
    size_t v0 = vt * 16 + g;
    int k0 = kt * 16 + tg * 2;
    const float* p00 = W_out + v0 * H + k0;
    float2 w00 = *reinterpret_cast<const float2*>(p00);            // a0
    float2 w01 = *reinterpret_cast<const float2*>(p00 + 8);        // a2
    float2 w10 = *reinterpret_cast<const float2*>(p00 + 8 * H);    // a1
    float2 w11 = *reinterpret_cast<const float2*>(p00 + 8 * H + 8);// a3
    uint4 f1, f2;
    cvt2(w00, f1.x, f2.x);
    cvt2(w10, f1.y, f2.y);
    cvt2(w01, f1.z, f2.z);
    cvt2(w11, f1.w, f2.w);
    g_w1f[frag * 32 + lane] = f1;
    g_w2f[frag * 32 + lane] = f2;
}

// ============================================================================
// P1: attn_x = sum_t encoder_out ; h0 = 0 ; attn output = ones ; tok0
// ============================================================================
extern "C" __global__ void p1_kernel(const float* __restrict__ enc,
                                     const int* __restrict__ y,
                                     float* __restrict__ d_out) {
    int gid  = blockIdx.x * blockDim.x + threadIdx.x;
    int nthr = gridDim.x * blockDim.x;
    if (gid < B) g_tok[gid] = y[gid * TOUT];     // y[b][0]
    for (int i = gid; i < B * H; i += nthr) {
        int b = i >> 9, k = i & 511;
        g_h[0][b][k] = 0.f;
        float s = 0.f;
        #pragma unroll 5
        for (int tt = 0; tt < TIN; tt++) s += enc[((size_t)b * TIN + tt) * H + k];
        g_attnx[b][k] = s;
    }
    float4 one4 = make_float4(1.f, 1.f, 1.f, 1.f);
    float4* dst = reinterpret_cast<float4*>(d_out + OFF_ATTN);
    size_t n4 = (size_t)TOUT * B * TIN * H / 4;
    for (size_t i = gid; i < n4; i += nthr) dst[i] = one4;
}

// ============================================================================
// MAIN persistent kernel
//   dynamic smem:
//     A/B/prologue: inp [32][257] (65792) + wtile [2][16][64] (16384) -> 82176
//     C:  Pw [512][36] u32 at 0 (73728, overlaps inp)
//         WST (HMMA W stage ring) at 82176: [8w][4st][2KB] = 65536
//         zt [256][33] f32 at 147712: 33792       -> total 181504
//   WST does not overlap A/B so phase B can prefetch C's first stages.
// ============================================================================
#define S_PAD 257
#define WST_OFF 82176
#define ZT_OFF  147712
extern "C" __global__ void __launch_bounds__(256, 1)
main_kernel(const float* __restrict__ emb,
            const float* __restrict__ W_comb, const float* __restrict__ b_comb,
            const float* __restrict__ W_hh,  const float* __restrict__ b_hh,
            const float* __restrict__ W_ih,  const float* __restrict__ b_ih,
            const float* __restrict__ b_out, float* __restrict__ d_out) {
    extern __shared__ char dsm[];
    ull* inp = reinterpret_cast<ull*>(dsm);                       // A/B: [32][S_PAD]
    ull* wtile = reinterpret_cast<ull*>(dsm + 65792);             // A/B: [2][16][64]

    __shared__ int   s_tok[B];
    __shared__ float sm_m[8][B], sm_s[8][B], sm_av[8][B];
    __shared__ int   sm_ai[8][B];
    __shared__ float sp[12][33];

    int tid = threadIdx.x, bid = blockIdx.x;
    int lane = tid & 31, w = tid >> 5;
    int g = lane >> 2, tg = lane & 3;
    unsigned gen = 0;   // barrier counter is reset to 0 at the end of each run

    // C-phase W-fragment pointers (also used by the B-phase prefetch)
    size_t gvt0 = (size_t)bid * 16 + 2 * w;
    const uint4* W1p = g_w1f + gvt0 * NKT * 32 + lane;
    const uint4* W2p = g_w2f + gvt0 * NKT * 32 + lane;
    unsigned wsa = sm_u32(dsm + WST_OFF) + w * 8192 + lane * 16;
    const char* wrd = dsm + WST_OFF + w * 8192 + lane * 16;

    // ============== prologue: c_attn (blocks 0..31, A-style) ==============
    if (bid < 32) {
        int row0 = bid * 16;
        const float* wbase = W_comb + H;
        const size_t wstride = 2 * H;
        #pragma unroll
        for (int cc = 0; cc < 2; cc++) {
            #pragma unroll
            for (int p = 0; p < 2; p++) {
                int idx = p * 256 + tid;
                int r = idx >> 5, jj = idx & 31;
                cpa16(sm_u32(&wtile[(size_t)cc * 1024 + r * 64 + jj * 2]),
                      wbase + (size_t)(row0 + r) * wstride + cc * 128 + jj * 4);
            }
            asm volatile("cp.async.commit_group;");
        }
        for (int i = tid; i < B * 256; i += 256) {
            int b = i >> 8, kq = i & 255;
            float2 v = *reinterpret_cast<const float2*>(&g_attnx[b][2 * kq]);
            *reinterpret_cast<float2*>(&inp[b * S_PAD + kq]) = v;
        }
        ull a00 = 0, a01 = 0, a10 = 0, a11 = 0;
        for (int c = 0; c < 4; c++) {
            if (c < 3) asm volatile("cp.async.wait_group 1;");
            else       asm volatile("cp.async.wait_group 0;");
            __syncthreads();
            const ull* wch = wtile + (size_t)(c & 1) * 1024;
            int r0 = (2 * w) * 64, r1 = (2 * w + 1) * 64;
            const ull* xrow = inp + lane * S_PAD + c * 64;
            #pragma unroll 8
            for (int q = 0; q < 64; q += 2) {
                ull x0 = xrow[q], x1 = xrow[q + 1];
                a00 = fma2(wch[r0 + q], x0, a00);
                a01 = fma2(wch[r0 + q + 1], x1, a01);
                a10 = fma2(wch[r1 + q], x0, a10);
                a11 = fma2(wch[r1 + q + 1], x1, a11);
            }
            __syncthreads();
            if (c < 2) {
                #pragma unroll
                for (int p = 0; p < 2; p++) {
                    int idx = p * 256 + tid;
                    int r = idx >> 5, jj = idx & 31;
                    cpa16(sm_u32(&wtile[(size_t)(c & 1) * 1024 + r * 64 + jj * 2]),
                          wbase + (size_t)(row0 + r) * wstride + (c + 2) * 128 + jj * 4);
                }
                asm volatile("cp.async.commit_group;");
            }
        }
        int o0 = row0 + 2 * w;
        g_cattn[lane][o0]     = sum2(a00) + sum2(a01) + b_comb[o0];
        g_cattn[lane][o0 + 1] = sum2(a10) + sum2(a11) + b_comb[o0 + 1];
    }
    gen = gsync(gen);

    int cur = 0;
    for (int t = 0; t < TOUT; t++) {
        // ========= Phase A: (xc blocks: merge->tok) + xc / gh GEMMs =========
        {
            bool is_xc = (bid < 32);
            int row0;
            const float* wbase;
            size_t wstride;
            if (is_xc) { row0 = bid * 16; wbase = W_comb; wstride = 2 * H; }
            else       { row0 = (bid - 32) * 16; wbase = W_hh; wstride = H; }

            #pragma unroll
            for (int cc = 0; cc < 2; cc++) {
                #pragma unroll
                for (int p = 0; p < 2; p++) {
                    int idx = p * 256 + tid;
                    int r = idx >> 5, jj = idx & 31;
                    cpa16(sm_u32(&wtile[(size_t)cc * 1024 + r * 64 + jj * 2]),
                          wbase + (size_t)(row0 + r) * wstride + cc * 128 + jj * 4);
                }
                asm volatile("cp.async.commit_group;");
            }

            if (is_xc) {
                if (t > 0) {
                    int b = lane, part = w;
                    float m = -INFINITY, s = 0.f, av = -INFINITY;
                    int ai = INT_MAX;
                    for (int i = part; i < NPB; i += 8) {
                        float pm = g_pmax[i][b];
                        float ps = g_psum[i][b];
                        int   pi = g_pidx[i][b];
                        if (pm > m) { s = s * __expf(m - pm) + ps; m = pm; }
                        else        { s += ps * __expf(pm - m); }
                        if (pm > av || (pm == av && pi < ai)) { av = pm; ai = pi; }
                    }
                    sm_m[part][b] = m; sm_s[part][b] = s;
                    sm_av[part][b] = av; sm_ai[part][b] = ai;
                    __syncthreads();
                    if (tid < B) {
                        float M = -INFINITY, S = 0.f, AV = -INFINITY;
                        int AI = INT_MAX;
                        #pragma unroll
                        for (int p = 0; p < 8; p++) {
                            float pm = sm_m[p][tid], ps = sm_s[p][tid];
                            if (pm > M) { S = S * __expf(M - pm) + ps; M = pm; }
                            else        { S += ps * __expf(pm - M); }
                            float v2 = sm_av[p][tid]; int i2 = sm_ai[p][tid];
                            if (v2 > AV || (v2 == AV && i2 < AI)) { AV = v2; AI = i2; }
                        }
                        s_tok[tid] = AI;
                        if (bid == 0) g_logZ[t - 1][tid] = M + logf(S);
                    }
                } else {
                    if (tid < B) s_tok[tid] = g_tok[tid];
                }
                __syncthreads();
            }

            for (int i = tid; i < B * 256; i += 256) {
                int b = i >> 8, kq = i & 255;
                const float* src = is_xc ? (emb + (size_t)s_tok[b] * H)
                                         : &g_h[cur][b][0];
                float2 v = *reinterpret_cast<const float2*>(src + 2 * kq);
                *reinterpret_cast<float2*>(&inp[b * S_PAD + kq]) = v;
            }

            ull a00 = 0, a01 = 0, a10 = 0, a11 = 0;
            for (int c = 0; c < 4; c++) {
                if (c < 3) asm volatile("cp.async.wait_group 1;");
                else       asm volatile("cp.async.wait_group 0;");
                __syncthreads();
                const ull* wch = wtile + (size_t)(c & 1) * 1024;
                int r0 = (2 * w) * 64, r1 = (2 * w + 1) * 64;
                const ull* xrow = inp + lane * S_PAD + c * 64;
                #pragma unroll 8
                for (int q = 0; q < 64; q += 2) {
                    ull x0 = xrow[q], x1 = xrow[q + 1];
                    a00 = fma2(wch[r0 + q], x0, a00);
                    a01 = fma2(wch[r0 + q + 1], x1, a01);
                    a10 = fma2(wch[r1 + q], x0, a10);
                    a11 = fma2(wch[r1 + q + 1], x1, a11);
                }
                __syncthreads();
                if (c < 2) {
                    #pragma unroll
                    for (int p = 0; p < 2; p++) {
                        int idx = p * 256 + tid;
                        int r = idx >> 5, jj = idx & 31;
                        cpa16(sm_u32(&wtile[(size_t)(c & 1) * 1024 + r * 64 + jj * 2]),
                              wbase + (size_t)(row0 + r) * wstride + (c + 2) * 128 + jj * 4);
                    }
                    asm volatile("cp.async.commit_group;");
                }
            }
            float v0 = sum2(a00) + sum2(a01);
            float v1 = sum2(a10) + sum2(a11);
            int o0 = row0 + 2 * w, o1 = o0 + 1;
            if (is_xc) {
                v0 += g_cattn[lane][o0];
                v1 += g_cattn[lane][o1];
                g_xc[lane][o0] = v0 > 0.f ? v0 : 0.f;
                g_xc[lane][o1] = v1 > 0.f ? v1 : 0.f;
            } else {
                g_gh[lane][o0] = v0 + b_hh[o0];
                g_gh[lane][o1] = v1 + b_hh[o1];
            }
        }
        gen = gsync(gen);

        // ========= Phase B: gi (12 rows/block) + GRU + pack h =========
        {
            int obase = bid * 4;
            #pragma unroll
            for (int cc = 0; cc < 2; cc++) {
                #pragma unroll
                for (int p = 0; p < 2; p++) {
                    int idx = p * 256 + tid;
                    if (idx < 384) {
                        int r = idx >> 5, jj = idx & 31;
                        int gg = r >> 2, ol = r & 3;
                        cpa16(sm_u32(&wtile[(size_t)cc * 1024 + r * 64 + jj * 2]),
                              W_ih + (size_t)(gg * H + obase + ol) * H + cc * 128 + jj * 4);
                    }
                }
                asm volatile("cp.async.commit_group;");
            }
            for (int i = tid; i < B * 256; i += 256) {
                int b = i >> 8, kq = i & 255;
                float2 v = *reinterpret_cast<const float2*>(&g_xc[b][2 * kq]);
                *reinterpret_cast<float2*>(&inp[b * S_PAD + kq]) = v;
            }
            ull a00 = 0, a01 = 0, a10 = 0, a11 = 0;
            for (int c = 0; c < 4; c++) {
                if (c < 3) asm volatile("cp.async.wait_group 1;");
                else       asm volatile("cp.async.wait_group 0;");
                __syncthreads();
                if (w < 6) {
                    const ull* wch = wtile + (size_t)(c & 1) * 1024;
                    int r0 = (2 * w) * 64, r1 = (2 * w + 1) * 64;
                    const ull* xrow = inp + lane * S_PAD + c * 64;
                    #pragma unroll 8
                    for (int q = 0; q < 64; q += 2) {
                        ull x0 = xrow[q], x1 = xrow[q + 1];
                        a00 = fma2(wch[r0 + q], x0, a00);
                        a01 = fma2(wch[r0 + q + 1], x1, a01);
                        a10 = fma2(wch[r1 + q], x0, a10);
                        a11 = fma2(wch[r1 + q + 1], x1, a11);
                    }
                }
                __syncthreads();
                if (c < 2) {
                    #pragma unroll
                    for (int p = 0; p < 2; p++) {
                        int idx = p * 256 + tid;
                        if (idx < 384) {
                            int r = idx >> 5, jj = idx & 31;
                            int gg = r >> 2, ol = r & 3;
                            cpa16(sm_u32(&wtile[(size_t)(c & 1) * 1024 + r * 64 + jj * 2]),
                                  W_ih + (size_t)(gg * H + obase + ol) * H + (c + 2) * 128 + jj * 4);
                        }
                    }
                    asm volatile("cp.async.commit_group;");
                }
            }
            if (w < 6) {
                sp[2 * w][lane]     = sum2(a00) + sum2(a01);
                sp[2 * w + 1][lane] = sum2(a10) + sum2(a11);
            }
            __syncthreads();
            if (tid < 128) {
                int b = tid & 31, ol = tid >> 5;
                int oo = obase + ol;
                float ir  = sp[ol][b]     + b_ih[oo];
                float iz  = sp[4 + ol][b] + b_ih[oo + H];
                float inn = sp[8 + ol][b] + b_ih[oo + 2 * H];
                float r  = 1.f / (1.f + expf(-(ir + g_gh[b][oo])));
                float zz = 1.f / (1.f + expf(-(iz + g_gh[b][oo + H])));
                float n  = tanhf(inn + r * g_gh[b][oo + 2 * H]);
                float hp = g_h[cur][b][oo];
                float hn = (1.f - zz) * n + zz * hp;
                g_h[cur ^ 1][b][oo] = hn;
                g_hpk[oo * 32 + b] = pack_h(hn);
                if (t == TOUT - 1) d_out[OFF_HT + (size_t)b * H + oo] = hn;
            }
            // ---- prefetch Phase C's first 3 W-frag stages (fly over gsync) --
            if (bid < NPB) {
                #pragma unroll
                for (int pre = 0; pre < 3; pre++) {
                    unsigned dst = wsa + pre * 2048;
                    cpa16(dst,        W1p + pre * 32);
                    cpa16(dst + 512,  W2p + pre * 32);
                    cpa16(dst + 1024, W1p + NKT * 32 + pre * 32);
                    cpa16(dst + 1536, W2p + NKT * 32 + pre * 32);
                    asm volatile("cp.async.commit_group;");
                }
            }
        }
        gen = gsync(gen);

        // ========= Phase C: z = h @ W_out^T + b_out via bf16x3 mma.sync =====
        if (bid < NPB) {
            unsigned* Pw = reinterpret_cast<unsigned*>(dsm);        // [512][36]
            float* zt = reinterpret_cast<float*>(dsm + ZT_OFF);     // [256][33]

            // stage packed h: Pw[k][36] = g_hpk[k][b]
            for (int i = tid; i < 4096; i += 256) {
                int k = i >> 3, b4 = (i & 7) * 4;
                uint4 v = *reinterpret_cast<const uint4*>(&g_hpk[k * 32 + b4]);
                *reinterpret_cast<uint4*>(&Pw[k * 36 + b4]) = v;
            }
            __syncthreads();

            float acc[2][4][4];
            #pragma unroll
            for (int a = 0; a < 2; a++)
                #pragma unroll
                for (int bb = 0; bb < 4; bb++)
                    #pragma unroll
                    for (int cc = 0; cc < 4; cc++) acc[a][bb][cc] = 0.f;

            for (int kt = 0; kt < NKT; kt++) {
                if (kt + 3 < NKT) {
                    int kn = kt + 3;
                    unsigned dst = wsa + (kn & 3) * 2048;
                    cpa16(dst,        W1p + kn * 32);
                    cpa16(dst + 512,  W2p + kn * 32);
                    cpa16(dst + 1024, W1p + NKT * 32 + kn * 32);
                    cpa16(dst + 1536, W2p + NKT * 32 + kn * 32);
                    asm volatile("cp.async.commit_group;");
                    asm volatile("cp.async.wait_group 3;");
                } else if (kt == NKT - 3) {
                    asm volatile("cp.async.wait_group 2;");
                } else if (kt == NKT - 2) {
                    asm volatile("cp.async.wait_group 1;");
                } else {
                    asm volatile("cp.async.wait_group 0;");
                }

                const char* stp = wrd + (kt & 3) * 2048;
                uint4 a1c0 = *reinterpret_cast<const uint4*>(stp);
                uint4 a2c0 = *reinterpret_cast<const uint4*>(stp + 512);
                uint4 a1c1 = *reinterpret_cast<const uint4*>(stp + 1024);
                uint4 a2c1 = *reinterpret_cast<const uint4*>(stp + 1536);

                unsigned bf1[4][2], bf2[4][2];
                #pragma unroll
                for (int bt = 0; bt < 4; bt++) {
                    int n = bt * 8 + g;
                    #pragma unroll
                    for (int r = 0; r < 2; r++) {
                        int k0 = kt * 16 + tg * 2 + r * 8;
                        unsigned e0 = Pw[k0 * 36 + n];
                        unsigned e1 = Pw[(k0 + 1) * 36 + n];
                        bf1[bt][r] = prmt(e0, e1, 0x5410u);
                        bf2[bt][r] = prmt(e0, e1, 0x7632u);
                    }
                }
                // term-outermost: 8 independent accumulators between reuses
                #pragma unroll
                for (int bt = 0; bt < 4; bt++) {
                    mma16816(acc[0][bt], a1c0, bf1[bt][0], bf1[bt][1]);
                    mma16816(acc[1][bt], a1c1, bf1[bt][0], bf1[bt][1]);
                }
                #pragma unroll
                for (int bt = 0; bt < 4; bt++) {
                    mma16816(acc[0][bt], a1c0, bf2[bt][0], bf2[bt][1]);
                    mma16816(acc[1][bt], a1c1, bf2[bt][0], bf2[bt][1]);
                }
                #pragma unroll
                for (int bt = 0; bt < 4; bt++) {
                    mma16816(acc[0][bt], a2c0, bf1[bt][0], bf1[bt][1]);
                    mma16816(acc[1][bt], a2c1, bf1[bt][0], bf1[bt][1]);
                }
            }

            int vbase = bid * VPB;
            #pragma unroll
            for (int vtl = 0; vtl < 2; vtl++) {
                int lv0 = (2 * w + vtl) * 16 + g;
                float bi0 = b_out[vbase + lv0];
                float bi8 = b_out[vbase + lv0 + 8];
                #pragma unroll
                for (int bt = 0; bt < 4; bt++) {
                    int bb = bt * 8 + tg * 2;
                    zt[lv0 * 33 + bb]           = acc[vtl][bt][0] + bi0;
                    zt[lv0 * 33 + bb + 1]       = acc[vtl][bt][1] + bi0;
                    zt[(lv0 + 8) * 33 + bb]     = acc[vtl][bt][2] + bi8;
                    zt[(lv0 + 8) * 33 + bb + 1] = acc[vtl][bt][3] + bi8;
                }
            }
            __syncthreads();

            // per-(b,seg) partials: warp spans b; skip exp when the whole warp
            // is >=18 below its local max (dropped mass <= 32000*e^-18 ~ 5e-4)
            {
                int b = tid & 31, seg = tid >> 5;
                float m = -INFINITY;
                int mi = 0;
                #pragma unroll 8
                for (int i = 0; i < 32; i++) {
                    int lv = seg * 32 + i;
                    float z = zt[lv * 33 + b];
                    if (z > m) { m = z; mi = vbase + lv; }
                }
                float s = 0.f;
                #pragma unroll 4
                for (int i = 0; i < 32; i++) {
                    int lv = seg * 32 + i;
                    float x = zt[lv * 33 + b] - m;
                    if (__any_sync(0xffffffffu, x > -18.f)) s += __expf(x);
                }
                sm_m[seg][b] = m; sm_s[seg][b] = s; sm_ai[seg][b] = mi;
            }
            // coalesced v-major zbuf writeout
            for (int j = tid; j < B * VPB; j += 256) {
                int b = j >> 8, lv = j & 255;
                __stcs(&g_zbuf[((size_t)t * B + b) * V + vbase + lv],
                       zt[lv * 33 + b]);
            }
            __syncthreads();
            if (tid < B) {
                int b = tid;
                float M = -INFINITY, S = 0.f;
                int I = INT_MAX;
                #pragma unroll
                for (int p = 0; p < 8; p++) {
                    float pm = sm_m[p][b], ps = sm_s[p][b];
                    if (pm > M) { S = S * __expf(M - pm) + ps; M = pm; I = sm_ai[p][b]; }
                    else        { S += ps * __expf(pm - M); }
                }
                g_pmax[bid][b] = M;
                g_psum[bid][b] = S;
                g_pidx[bid][b] = I;
            }
        }
        gen = gsync(gen);
        cur ^= 1;
    }

    // ---------------- final logZ[TOUT-1] (block 0) ----------------
    if (bid == 0) {
        int b = lane, part = w;
        float m = -INFINITY, s = 0.f;
        for (int i = part; i < NPB; i += 8) {
            float pm = g_pmax[i][b], ps = g_psum[i][b];
            if (pm > m) { s = s * __expf(m - pm) + ps; m = pm; }
            else        { s += ps * __expf(pm - m); }
        }
        sm_m[part][b] = m; sm_s[part][b] = s;
        __syncthreads();
        if (tid < B) {
            float M = -INFINITY, S = 0.f;
            #pragma unroll
            for (int p = 0; p < 8; p++) {
                float pm = sm_m[p][tid], ps = sm_s[p][tid];
                if (pm > M) { S = S * __expf(M - pm) + ps; M = pm; }
                else        { S += ps * __expf(pm - M); }
            }
            g_logZ[TOUT - 1][tid] = M + logf(S);
        }
    }

    // final barrier + counter reset (for graph replay determinism)
    gen = gsync(gen);
    if (bid == 0 && tid == 0) {
        asm volatile("st.release.gpu.global.u32 [%0], %1;"
                     :: "l"(&g_bar_cnt), "r"(0u) : "memory");
    }
}

// ============================================================================
// E2: out[b][v][t] = z[t][b][v] - logZ[t][b]   (smem-tiled transpose)
// ============================================================================
extern "C" __global__ void __launch_bounds__(256)
e2_kernel(float* __restrict__ d_out) {
    __shared__ float s_z[128][53];
    __shared__ float s_lz[TOUT];
    int b = blockIdx.y;
    int v0 = blockIdx.x * 128;
    int tid = threadIdx.x;
    if (tid < TOUT) s_lz[tid] = g_logZ[tid][b];
    __syncthreads();
    for (int j = tid; j < 128 * TOUT; j += 256) {
        int tt = j >> 7, vl = j & 127;
        s_z[vl][tt] = __ldcs(&g_zbuf[((size_t)tt * B + b) * V + v0 + vl]) - s_lz[tt];
    }
    __syncthreads();
    size_t base = ((size_t)b * V + v0) * TOUT;
    for (int j = tid; j < 128 * TOUT; j += 256) {
        int vl = j / TOUT, tt = j % TOUT;
        d_out[base + j] = s_z[vl][tt];
    }
}

// ============================================================================
extern "C" void kernel_launch(void* const* d_in, const int* in_sizes, int n_in,
                              void* d_out_v, int out_size) {
    const float* enc    = (const float*)d_in[0];
    const int*   y      = (const int*)d_in[1];
    const float* emb    = (const float*)d_in[2];
    // d_in[3..6]: W_fc, b_fc, W_fc1, W_fc2 — dead (softmax over singleton axis)
    const float* W_comb = (const float*)d_in[7];
    const float* b_comb = (const float*)d_in[8];
    const float* W_ih   = (const float*)d_in[9];
    const float* W_hh   = (const float*)d_in[10];
    const float* b_ih   = (const float*)d_in[11];
    const float* b_hh   = (const float*)d_in[12];
    const float* W_out  = (const float*)d_in[13];
    const float* b_out  = (const float*)d_in[14];
    float* d_out = (float*)d_out_v;

    const int main_smem = ZT_OFF + 256 * 33 * 4;   // 181504
    cudaFuncSetAttribute(main_kernel, cudaFuncAttributeMaxDynamicSharedMemorySize,
                         main_smem);

    p0_kernel<<<(NVT * NKT * 32) / 256, 256>>>(W_out);
    p1_kernel<<<512, 256>>>(enc, y, d_out);
    main_kernel<<<GRID, 256, main_smem>>>(emb, W_comb, b_comb, W_hh, b_hh,
                                          W_ih, b_ih, b_out, d_out);
    e2_kernel<<<dim3(V / 128, B), 256>>>(d_out);
}